// round 13
// baseline (speedup 1.0000x reference)
#include <cuda_runtime.h>
#include <cstdint>

#define S_LEN 4096
#define EMB   1024
#define HEAD  64
#define BATCH 4
#define M_TOTAL (BATCH * S_LEN)   // 16384

__device__ float g_QKV[3][M_TOTAL * HEAD];

// ---------------------------------------------------------------------------
// helpers
// ---------------------------------------------------------------------------
__device__ __forceinline__ uint32_t f2tf(float f) {
    uint32_t r;
    asm("cvt.rna.tf32.f32 %0, %1;" : "=r"(r) : "f"(f));
    return r;
}

__device__ __forceinline__ float ex2(float x) {
    float y;
    asm("ex2.approx.f32 %0, %1;" : "=f"(y) : "f"(x));
    return y;
}

__device__ __forceinline__ void mma_tf32(float c[4],
                                         const uint32_t a[4],
                                         const uint32_t b[2]) {
    asm volatile(
        "mma.sync.aligned.m16n8k8.row.col.f32.tf32.tf32.f32 "
        "{%0,%1,%2,%3}, {%4,%5,%6,%7}, {%8,%9}, {%0,%1,%2,%3};\n"
        : "+f"(c[0]), "+f"(c[1]), "+f"(c[2]), "+f"(c[3])
        : "r"(a[0]), "r"(a[1]), "r"(a[2]), "r"(a[3]),
          "r"(b[0]), "r"(b[1]));
}

__device__ __forceinline__ void cp16(float* s, const float* g) {
    uint32_t sa = (uint32_t)__cvta_generic_to_shared(s);
    asm volatile("cp.async.cg.shared.global [%0], [%1], 16;\n"
                 :: "r"(sa), "l"(g));
}
#define CP_COMMIT() asm volatile("cp.async.commit_group;\n")
#define CP_WAIT0()  asm volatile("cp.async.wait_group 0;\n")
#define CP_WAIT1()  asm volatile("cp.async.wait_group 1;\n")

__device__ __forceinline__ void barg(int g) {   // per-group named barrier
    asm volatile("bar.sync %0, 128;" :: "r"(g + 1) : "memory");
}

// ---------------------------------------------------------------------------
// Kernel 1: FUSED QKV projection. BM=64, BK=32, 256 thr (8 warps:
// 4 m-tiles x 2 n-halves). Raw W consumed directly (no prep kernel):
// natural [k][n] stride-72 smem tiles, RNA tf32 at fragment build
// (bank-free: addr mod 32 = 8c+r, bijective).
// Outputs: Q natural; K column-pair permuted; V row-pair interleaved.
// ---------------------------------------------------------------------------
#define QKV_AS(buf)  (sm + (buf) * 2304)          // 64*36
#define QKV_BS(buf)  (sm + 4608 + (buf) * 6912)   // 3 * 32*72
#define QKV_SMEM_BYTES 73728

__global__ __launch_bounds__(256) void qkv_kernel(const float* __restrict__ x,
    const float* __restrict__ Wq, const float* __restrict__ Wk,
    const float* __restrict__ Wv,
    const float* __restrict__ bq, const float* __restrict__ bk,
    const float* __restrict__ bv)
{
    extern __shared__ float sm[];

    const int t    = threadIdx.x;
    const int lane = t & 31;
    const int warp = t >> 5;
    const int m0   = (warp >> 1) * 16;
    const int n0   = (warp & 1) * 32;
    const int row0 = blockIdx.x * 64;

    const int r = lane >> 2;
    const int c = lane & 3;

    const float* Wp[3] = { Wq, Wk, Wv };

    auto prefetch = [&](int k0, int buf) {
        float* Ab = QKV_AS(buf);
        float* Bb = QKV_BS(buf);
        #pragma unroll
        for (int i = 0; i < 2; i++) {              // 512 cp16: x tile 64x32
            int idx = t + 256 * i;
            int m = idx >> 3, ch = idx & 7;
            cp16(Ab + m * 36 + ch * 4, x + (row0 + m) * EMB + k0 + ch * 4);
        }
        #pragma unroll
        for (int w = 0; w < 3; w++) {              // 3 x 512 cp16: raw W tiles
            #pragma unroll
            for (int i = 0; i < 2; i++) {
                int idx = t + 256 * i;
                int k = idx >> 4, ch = idx & 15;
                cp16(Bb + w * 2304 + k * 72 + ch * 4,
                     Wp[w] + (k0 + k) * HEAD + ch * 4);
            }
        }
    };

    float acc[3][4][4] = {};

    prefetch(0, 0);
    CP_COMMIT();

    for (int step = 0; step < 32; step++) {
        const int cur = step & 1;
        CP_WAIT0();
        __syncthreads();
        if (step < 31) { prefetch((step + 1) * 32, cur ^ 1); CP_COMMIT(); }

        const float* Ab = QKV_AS(cur);
        const float* Bb = QKV_BS(cur);

        #pragma unroll
        for (int ks = 0; ks < 4; ks++) {
            const float* ap = Ab + (m0 + r) * 36 + ks * 8 + c;
            uint32_t af[4];
            af[0] = f2tf(ap[0]);
            af[1] = f2tf(ap[8 * 36]);
            af[2] = f2tf(ap[4]);
            af[3] = f2tf(ap[8 * 36 + 4]);
            #pragma unroll
            for (int w = 0; w < 3; w++) {
                #pragma unroll
                for (int nt = 0; nt < 4; nt++) {
                    const float* bp = Bb + w * 2304 + (ks * 8 + c) * 72 +
                                      n0 + nt * 8 + r;
                    uint32_t bf[2] = { f2tf(bp[0]), f2tf(bp[4 * 72]) };
                    mma_tf32(acc[w][nt], af, bf);
                }
            }
        }
        __syncthreads();
    }

    // ---- epilogue: +bias, per-which output layouts ----
    const int j  = 2 * c;
    const int p0 = 2 * (j & 3) + (j >> 2);
    const int p1 = 2 * ((j + 1) & 3) + ((j + 1) >> 2);
    const int mA = row0 + m0 + r;
    const int mB = mA + 8;

    #pragma unroll
    for (int w = 0; w < 3; w++) {
        const float* bias = (w == 0) ? bq : (w == 1) ? bk : bv;
        float* out = g_QKV[w];
        #pragma unroll
        for (int nt = 0; nt < 4; nt++) {
            int n = n0 + nt * 8 + 2 * c;
            float b0 = bias[n], b1 = bias[n + 1];
            float v00 = acc[w][nt][0] + b0, v01 = acc[w][nt][1] + b1;
            float v10 = acc[w][nt][2] + b0, v11 = acc[w][nt][3] + b1;

            if (w == 0) {
                *(float2*)&out[mA * HEAD + n] = make_float2(v00, v01);
                *(float2*)&out[mB * HEAD + n] = make_float2(v10, v11);
            } else if (w == 1) {
                int base8 = n0 + nt * 8;
                out[mA * HEAD + base8 + p0] = __uint_as_float(f2tf(v00));
                out[mA * HEAD + base8 + p1] = __uint_as_float(f2tf(v01));
                out[mB * HEAD + base8 + p0] = __uint_as_float(f2tf(v10));
                out[mB * HEAD + base8 + p1] = __uint_as_float(f2tf(v11));
            } else {
                int baseA = (mA >> 3) * 512 + (mA & 3) * 128 + ((mA >> 2) & 1);
                int baseB = (mB >> 3) * 512 + (mB & 3) * 128 + ((mB >> 2) & 1);
                out[baseA + 2 * n]       = __uint_as_float(f2tf(v00));
                out[baseA + 2 * (n + 1)] = __uint_as_float(f2tf(v01));
                out[baseB + 2 * n]       = __uint_as_float(f2tf(v10));
                out[baseB + 2 * (n + 1)] = __uint_as_float(f2tf(v11));
            }
        }
    }
}

// ---------------------------------------------------------------------------
// Kernel 2: causal flash attention (unchanged from R11: in-block split-KV,
// rebalanced remap, paired K/V layouts, ex2 softmax).
// ---------------------------------------------------------------------------
#define ATT_KG(g)   (sm + (g) * 8960)
#define ATT_VG(g)   (sm + (g) * 8960 + 4608)
#define ATT_PS      (sm + 17920)
#define ATT_SMEM_BYTES 106496

#define QSCALE 0.1803368801111354f    // (1/8) * log2(e)

__global__ __launch_bounds__(256, 2) void attn_kernel(float* __restrict__ out)
{
    extern __shared__ float sm[];

    const float* Q = g_QKV[0];
    const float* K = g_QKV[1];
    const float* V = g_QKV[2];

    // ---- rebalanced work remap (classic placement: SM = bid % 148) ----
    const int lid = blockIdx.x + 64 * blockIdx.y;   // 0..255
    int qb, b;
    if (lid < 80)        { qb = 63 - (lid >> 2);             b = lid & 3; }
    else if (lid < 108)  { int k = lid - 80;  qb = 33 - (k >> 2); b = k & 3; }
    else if (lid < 148)  { int k = lid - 108; qb = 34 + (k >> 2); b = k & 3; }
    else if (lid < 228)  { int k = lid - 148; qb = k >> 2;        b = k & 3; }
    else                 { int k = lid - 228; qb = 20 + (k >> 2); b = k & 3; }

    const int t    = threadIdx.x;
    const int lane = t & 31;
    const int warp = t >> 5;
    const int g    = warp >> 2;
    const int lw   = warp & 3;
    const int t128 = t & 127;
    const int base = b * S_LEN * HEAD;

    const int r = lane >> 2;
    const int c = lane & 3;

    float* Kb  = ATT_KG(g);
    float* Vb  = ATT_VG(g);
    float* Psw = ATT_PS + warp * 1088;

    auto pfK = [&](int kb) {
        const float* Kg = K + base + kb * 64 * HEAD;
        #pragma unroll
        for (int i = 0; i < 8; i++) {
            int idx = t128 + 128 * i;
            int row = idx >> 4, ch = idx & 15;
            cp16(Kb + row * 72 + ch * 4, Kg + row * 64 + ch * 4);
        }
    };
    auto pfV = [&](int kb) {
        const float* Vg = V + base + kb * 64 * HEAD;
        #pragma unroll
        for (int i = 0; i < 8; i++) {
            int idx = t128 + 128 * i;
            int row = idx >> 5, ch = idx & 31;
            cp16(Vb + row * 136 + ch * 4, Vg + row * 128 + ch * 4);
        }
    };

    uint32_t qa[8][4];
    {
        const int qrow = qb * 64 + lw * 16 + r;
        #pragma unroll
        for (int kt = 0; kt < 8; kt++) {
            int d = kt * 8 + c;
            qa[kt][0] = f2tf(Q[base + qrow * HEAD + d] * QSCALE);
            qa[kt][1] = f2tf(Q[base + (qrow + 8) * HEAD + d] * QSCALE);
            qa[kt][2] = f2tf(Q[base + qrow * HEAD + d + 4] * QSCALE);
            qa[kt][3] = f2tf(Q[base + (qrow + 8) * HEAD + d + 4] * QSCALE);
        }
    }

    float oacc[8][4] = {};
    float mA = -1e30f, mB = -1e30f, lA = 0.0f, lB = 0.0f;

    if (g <= qb) {
        pfK(g); CP_COMMIT();
        pfV(g); CP_COMMIT();
    }

    for (int kb = g; kb <= qb; kb += 2) {
        CP_WAIT1();
        barg(g);

        float sacc[8][4] = {};
        #pragma unroll
        for (int dk = 0; dk < 8; dk++) {
            #pragma unroll
            for (int nt = 0; nt < 8; nt++) {
                float2 kk = *(const float2*)(Kb + (nt * 8 + r) * 72 + dk * 8 + 2 * c);
                uint32_t bfrag[2] = { __float_as_uint(kk.x), __float_as_uint(kk.y) };
                mma_tf32(sacc[nt], qa[dk], bfrag);
            }
        }

        barg(g);
        if (kb + 2 <= qb) pfK(kb + 2);
        CP_COMMIT();

        if (kb == qb) {
            int qA = lw * 16 + r;
            int qB = qA + 8;
            #pragma unroll
            for (int nt = 0; nt < 8; nt++) {
                int k0l = nt * 8 + 2 * c;
                if (k0l     > qA) sacc[nt][0] = -1e30f;
                if (k0l + 1 > qA) sacc[nt][1] = -1e30f;
                if (k0l     > qB) sacc[nt][2] = -1e30f;
                if (k0l + 1 > qB) sacc[nt][3] = -1e30f;
            }
        }

        {
            float mxA = -1e30f, mxB = -1e30f;
            #pragma unroll
            for (int nt = 0; nt < 8; nt++) {
                mxA = fmaxf(mxA, fmaxf(sacc[nt][0], sacc[nt][1]));
                mxB = fmaxf(mxB, fmaxf(sacc[nt][2], sacc[nt][3]));
            }
            mxA = fmaxf(mxA, __shfl_xor_sync(0xffffffffu, mxA, 1, 4));
            mxA = fmaxf(mxA, __shfl_xor_sync(0xffffffffu, mxA, 2, 4));
            mxB = fmaxf(mxB, __shfl_xor_sync(0xffffffffu, mxB, 1, 4));
            mxB = fmaxf(mxB, __shfl_xor_sync(0xffffffffu, mxB, 2, 4));
            float mnA = fmaxf(mA, mxA);
            float mnB = fmaxf(mB, mxB);
            float alA = ex2(mA - mnA);
            float alB = ex2(mB - mnB);
            mA = mnA; mB = mnB;
            float rsA = 0.0f, rsB = 0.0f;
            #pragma unroll
            for (int nt = 0; nt < 8; nt++) {
                sacc[nt][0] = ex2(sacc[nt][0] - mnA);
                sacc[nt][1] = ex2(sacc[nt][1] - mnA);
                sacc[nt][2] = ex2(sacc[nt][2] - mnB);
                sacc[nt][3] = ex2(sacc[nt][3] - mnB);
                rsA += sacc[nt][0] + sacc[nt][1];
                rsB += sacc[nt][2] + sacc[nt][3];
            }
            rsA += __shfl_xor_sync(0xffffffffu, rsA, 1, 4);
            rsA += __shfl_xor_sync(0xffffffffu, rsA, 2, 4);
            rsB += __shfl_xor_sync(0xffffffffu, rsB, 1, 4);
            rsB += __shfl_xor_sync(0xffffffffu, rsB, 2, 4);
            lA = lA * alA + rsA;
            lB = lB * alB + rsB;
            #pragma unroll
            for (int dt = 0; dt < 8; dt++) {
                oacc[dt][0] *= alA; oacc[dt][1] *= alA;
                oacc[dt][2] *= alB; oacc[dt][3] *= alB;
            }
        }

        #pragma unroll
        for (int nt = 0; nt < 8; nt++) {
            int col = nt * 8 + 2 * c;
            uint2 p0, p1;
            p0.x = f2tf(sacc[nt][0]); p0.y = f2tf(sacc[nt][1]);
            p1.x = f2tf(sacc[nt][2]); p1.y = f2tf(sacc[nt][3]);
            *(uint2*)&Psw[r * 68 + col]       = p0;
            *(uint2*)&Psw[(r + 8) * 68 + col] = p1;
        }
        __syncwarp();

        CP_WAIT1();
        barg(g);

        #pragma unroll
        for (int kt = 0; kt < 8; kt++) {
            uint32_t pa[4];
            pa[0] = __float_as_uint(Psw[r * 68 + kt * 8 + c]);
            pa[1] = __float_as_uint(Psw[(r + 8) * 68 + kt * 8 + c]);
            pa[2] = __float_as_uint(Psw[r * 68 + kt * 8 + c + 4]);
            pa[3] = __float_as_uint(Psw[(r + 8) * 68 + kt * 8 + c + 4]);
            #pragma unroll
            for (int dt = 0; dt < 8; dt++) {
                float2 vv = *(const float2*)(Vb + (kt * 4 + c) * 136 + (dt * 8 + r) * 2);
                uint32_t vbf[2] = { __float_as_uint(vv.x), __float_as_uint(vv.y) };
                mma_tf32(oacc[dt], pa, vbf);
            }
        }

        barg(g);
        if (kb + 2 <= qb) pfV(kb + 2);
        CP_COMMIT();
    }

    // ---- merge split-KV partials ----
    float* MS = sm;
    __syncthreads();
    if (g == 1) {
        float* p = MS + t128 * 37;
        #pragma unroll
        for (int dt = 0; dt < 8; dt++) {
            p[dt * 4 + 0] = oacc[dt][0]; p[dt * 4 + 1] = oacc[dt][1];
            p[dt * 4 + 2] = oacc[dt][2]; p[dt * 4 + 3] = oacc[dt][3];
        }
        p[32] = mA; p[33] = mB; p[34] = lA; p[35] = lB;
    }
    __syncthreads();
    if (g == 0) {
        const float* p = MS + t128 * 37;
        float m1A = p[32], m1B = p[33], l1A = p[34], l1B = p[35];
        float mnA = fmaxf(mA, m1A);
        float mnB = fmaxf(mB, m1B);
        float w0A = ex2(mA - mnA), w1A = ex2(m1A - mnA);
        float w0B = ex2(mB - mnB), w1B = ex2(m1B - mnB);
        float invA = 1.0f / (lA * w0A + l1A * w1A);
        float invB = 1.0f / (lB * w0B + l1B * w1B);
        int qrow = qb * 64 + lw * 16 + r;
        #pragma unroll
        for (int dt = 0; dt < 8; dt++) {
            float o0 = (oacc[dt][0] * w0A + p[dt * 4 + 0] * w1A) * invA;
            float o1 = (oacc[dt][1] * w0A + p[dt * 4 + 1] * w1A) * invA;
            float o2 = (oacc[dt][2] * w0B + p[dt * 4 + 2] * w1B) * invB;
            float o3 = (oacc[dt][3] * w0B + p[dt * 4 + 3] * w1B) * invB;
            int d = dt * 8 + 2 * c;
            *(float2*)&out[base + qrow * HEAD + d]       = make_float2(o0, o1);
            *(float2*)&out[base + (qrow + 8) * HEAD + d] = make_float2(o2, o3);
        }
    }
}

// ---------------------------------------------------------------------------
extern "C" void kernel_launch(void* const* d_in, const int* in_sizes, int n_in,
                              void* d_out, int out_size)
{
    const float* x  = (const float*)d_in[0];
    const float* Wq = (const float*)d_in[1];
    const float* bq = (const float*)d_in[2];
    const float* Wk = (const float*)d_in[3];
    const float* bk = (const float*)d_in[4];
    const float* Wv = (const float*)d_in[5];
    const float* bv = (const float*)d_in[6];
    float* out = (float*)d_out;

    cudaFuncSetAttribute(qkv_kernel,
        cudaFuncAttributeMaxDynamicSharedMemorySize, QKV_SMEM_BYTES);
    cudaFuncSetAttribute(attn_kernel,
        cudaFuncAttributeMaxDynamicSharedMemorySize, ATT_SMEM_BYTES);

    qkv_kernel<<<M_TOTAL / 64, 256, QKV_SMEM_BYTES>>>(x, Wq, Wk, Wv,
                                                      bq, bk, bv);

    dim3 g2(S_LEN / 64, BATCH);
    attn_kernel<<<g2, 256, ATT_SMEM_BYTES>>>(out);
}

// round 14
// speedup vs baseline: 1.1657x; 1.1657x over previous
#include <cuda_runtime.h>
#include <cstdint>

#define S_LEN 4096
#define EMB   1024
#define HEAD  64
#define BATCH 4
#define M_TOTAL (BATCH * S_LEN)   // 16384

__device__ float g_QKV[3][M_TOTAL * HEAD];
__device__ float g_W[3][EMB * HEAD];       // pre-rounded, b-frag-paired layout

// ---------------------------------------------------------------------------
// helpers
// ---------------------------------------------------------------------------
__device__ __forceinline__ uint32_t f2tf(float f) {
    uint32_t r;
    asm("cvt.rna.tf32.f32 %0, %1;" : "=r"(r) : "f"(f));
    return r;
}

__device__ __forceinline__ float ex2(float x) {
    float y;
    asm("ex2.approx.f32 %0, %1;" : "=f"(y) : "f"(x));
    return y;
}

__device__ __forceinline__ void mma_tf32(float c[4],
                                         const uint32_t a[4],
                                         const uint32_t b[2]) {
    asm volatile(
        "mma.sync.aligned.m16n8k8.row.col.f32.tf32.tf32.f32 "
        "{%0,%1,%2,%3}, {%4,%5,%6,%7}, {%8,%9}, {%0,%1,%2,%3};\n"
        : "+f"(c[0]), "+f"(c[1]), "+f"(c[2]), "+f"(c[3])
        : "r"(a[0]), "r"(a[1]), "r"(a[2]), "r"(a[3]),
          "r"(b[0]), "r"(b[1]));
}

__device__ __forceinline__ void cp16(float* s, const float* g) {
    uint32_t sa = (uint32_t)__cvta_generic_to_shared(s);
    asm volatile("cp.async.cg.shared.global [%0], [%1], 16;\n"
                 :: "r"(sa), "l"(g));
}
#define CP_COMMIT() asm volatile("cp.async.commit_group;\n")
#define CP_WAIT0()  asm volatile("cp.async.wait_group 0;\n")
#define CP_WAIT1()  asm volatile("cp.async.wait_group 1;\n")

__device__ __forceinline__ void barg(int g) {   // per-group named barrier
    asm volatile("bar.sync %0, 128;" :: "r"(g + 1) : "memory");
}

// ---------------------------------------------------------------------------
// Kernel 0: W prep. RNA-round W to tf32, paired layout:
//   (k, n) -> g_W[which][((k>>3)*64 + n)*8 + 2*(u&3) + (u>>2)], u = k&7
// (768-block variant: 1 element/thread — measured fastest)
// ---------------------------------------------------------------------------
__global__ void wprep_kernel(const float* __restrict__ Wq,
                             const float* __restrict__ Wk,
                             const float* __restrict__ Wv)
{
    const float* src = (blockIdx.y == 0) ? Wq : (blockIdx.y == 1) ? Wk : Wv;
    int idx = blockIdx.x * 256 + threadIdx.x;    // 0 .. EMB*HEAD-1
    int k = idx >> 6, n = idx & 63;
    int u = k & 7, a = k >> 3;
    g_W[blockIdx.y][(a * 64 + n) * 8 + 2 * (u & 3) + (u >> 2)] =
        __uint_as_float(f2tf(src[idx]));
}

// ---------------------------------------------------------------------------
// Kernel 1: FUSED QKV projection (BM=64, BK=32, 256 thr, 8 warps:
// 4 m-tiles x 2 n-halves; 256 blocks -> full chip).
// As: raw fp32 [m][k] stride 36; Bs: paired tf32 [which*4+a][n][pair].
// Outputs: Q natural; K column-pair permuted; V row-pair interleaved.
// ---------------------------------------------------------------------------
#define QKV_AS(buf)  (sm + (buf) * 2304)          // 64*36
#define QKV_BS(buf)  (sm + 4608 + (buf) * 6144)   // 12*512
#define QKV_SMEM_BYTES 67584

__global__ __launch_bounds__(256) void qkv_kernel(const float* __restrict__ x,
    const float* __restrict__ bq, const float* __restrict__ bk,
    const float* __restrict__ bv)
{
    extern __shared__ float sm[];

    const int t    = threadIdx.x;
    const int lane = t & 31;
    const int warp = t >> 5;
    const int m0   = (warp >> 1) * 16;
    const int n0   = (warp & 1) * 32;
    const int row0 = blockIdx.x * 64;

    const int r = lane >> 2;
    const int c = lane & 3;

    auto prefetch = [&](int k0, int buf) {
        float* Ab = QKV_AS(buf);
        float* Bb = QKV_BS(buf);
        #pragma unroll
        for (int i = 0; i < 2; i++) {              // 512 cp16: x tile 64x32
            int idx = t + 256 * i;
            int m = idx >> 3, ch = idx & 7;
            cp16(Ab + m * 36 + ch * 4, x + (row0 + m) * EMB + k0 + ch * 4);
        }
        const int s = k0 >> 5;
        #pragma unroll
        for (int i = 0; i < 6; i++) {              // 1536 cp16: 3 W tiles
            int idx = t + 256 * i;
            int blk = idx >> 7;                    // which*4 + a
            int off = (idx & 127) * 4;
            cp16(Bb + blk * 512 + off,
                 g_W[blk >> 2] + ((s * 4 + (blk & 3)) * 512 + off));
        }
    };

    float acc[3][4][4] = {};

    prefetch(0, 0);
    CP_COMMIT();

    for (int step = 0; step < 32; step++) {
        const int cur = step & 1;
        CP_WAIT0();
        __syncthreads();
        if (step < 31) { prefetch((step + 1) * 32, cur ^ 1); CP_COMMIT(); }

        const float* Ab = QKV_AS(cur);
        const float* Bb = QKV_BS(cur);

        #pragma unroll
        for (int ks = 0; ks < 4; ks++) {
            const float* ap = Ab + (m0 + r) * 36 + ks * 8 + c;
            uint32_t af[4];
            af[0] = f2tf(ap[0]);
            af[1] = f2tf(ap[8 * 36]);
            af[2] = f2tf(ap[4]);
            af[3] = f2tf(ap[8 * 36 + 4]);
            #pragma unroll
            for (int w = 0; w < 3; w++) {
                #pragma unroll
                for (int nt = 0; nt < 4; nt++) {
                    float2 bb = *(const float2*)(Bb + (w * 4 + ks) * 512 +
                                                 (n0 + nt * 8 + r) * 8 + 2 * c);
                    uint32_t bf[2] = { __float_as_uint(bb.x),
                                       __float_as_uint(bb.y) };
                    mma_tf32(acc[w][nt], af, bf);
                }
            }
        }
        __syncthreads();
    }

    // ---- epilogue: +bias, per-which output layouts ----
    const int j  = 2 * c;
    const int p0 = 2 * (j & 3) + (j >> 2);
    const int p1 = 2 * ((j + 1) & 3) + ((j + 1) >> 2);
    const int mA = row0 + m0 + r;
    const int mB = mA + 8;

    #pragma unroll
    for (int w = 0; w < 3; w++) {
        const float* bias = (w == 0) ? bq : (w == 1) ? bk : bv;
        float* out = g_QKV[w];
        #pragma unroll
        for (int nt = 0; nt < 4; nt++) {
            int n = n0 + nt * 8 + 2 * c;
            float b0 = bias[n], b1 = bias[n + 1];
            float v00 = acc[w][nt][0] + b0, v01 = acc[w][nt][1] + b1;
            float v10 = acc[w][nt][2] + b0, v11 = acc[w][nt][3] + b1;

            if (w == 0) {
                *(float2*)&out[mA * HEAD + n] = make_float2(v00, v01);
                *(float2*)&out[mB * HEAD + n] = make_float2(v10, v11);
            } else if (w == 1) {
                int base8 = n0 + nt * 8;
                out[mA * HEAD + base8 + p0] = __uint_as_float(f2tf(v00));
                out[mA * HEAD + base8 + p1] = __uint_as_float(f2tf(v01));
                out[mB * HEAD + base8 + p0] = __uint_as_float(f2tf(v10));
                out[mB * HEAD + base8 + p1] = __uint_as_float(f2tf(v11));
            } else {
                int baseA = (mA >> 3) * 512 + (mA & 3) * 128 + ((mA >> 2) & 1);
                int baseB = (mB >> 3) * 512 + (mB & 3) * 128 + ((mB >> 2) & 1);
                out[baseA + 2 * n]       = __uint_as_float(f2tf(v00));
                out[baseA + 2 * (n + 1)] = __uint_as_float(f2tf(v01));
                out[baseB + 2 * n]       = __uint_as_float(f2tf(v10));
                out[baseB + 2 * (n + 1)] = __uint_as_float(f2tf(v11));
            }
        }
    }
}

// ---------------------------------------------------------------------------
// Kernel 2: causal flash attention (R11 body): in-block split-KV, rebalanced
// remap (singles get mid-weight work), paired K/V layouts, ex2 softmax.
// ---------------------------------------------------------------------------
#define ATT_KG(g)   (sm + (g) * 8960)
#define ATT_VG(g)   (sm + (g) * 8960 + 4608)
#define ATT_PS      (sm + 17920)
#define ATT_SMEM_BYTES 106496

#define QSCALE 0.1803368801111354f    // (1/8) * log2(e)

__global__ __launch_bounds__(256, 2) void attn_kernel(float* __restrict__ out)
{
    extern __shared__ float sm[];

    const float* Q = g_QKV[0];
    const float* K = g_QKV[1];
    const float* V = g_QKV[2];

    // ---- rebalanced work remap (classic placement: SM = bid % 148) ----
    const int lid = blockIdx.x + 64 * blockIdx.y;   // 0..255
    int qb, b;
    if (lid < 80)        { qb = 63 - (lid >> 2);             b = lid & 3; }
    else if (lid < 108)  { int k = lid - 80;  qb = 33 - (k >> 2); b = k & 3; }
    else if (lid < 148)  { int k = lid - 108; qb = 34 + (k >> 2); b = k & 3; }
    else if (lid < 228)  { int k = lid - 148; qb = k >> 2;        b = k & 3; }
    else                 { int k = lid - 228; qb = 20 + (k >> 2); b = k & 3; }

    const int t    = threadIdx.x;
    const int lane = t & 31;
    const int warp = t >> 5;
    const int g    = warp >> 2;
    const int lw   = warp & 3;
    const int t128 = t & 127;
    const int base = b * S_LEN * HEAD;

    const int r = lane >> 2;
    const int c = lane & 3;

    float* Kb  = ATT_KG(g);
    float* Vb  = ATT_VG(g);
    float* Psw = ATT_PS + warp * 1088;

    auto pfK = [&](int kb) {
        const float* Kg = K + base + kb * 64 * HEAD;
        #pragma unroll
        for (int i = 0; i < 8; i++) {
            int idx = t128 + 128 * i;
            int row = idx >> 4, ch = idx & 15;
            cp16(Kb + row * 72 + ch * 4, Kg + row * 64 + ch * 4);
        }
    };
    auto pfV = [&](int kb) {
        const float* Vg = V + base + kb * 64 * HEAD;
        #pragma unroll
        for (int i = 0; i < 8; i++) {
            int idx = t128 + 128 * i;
            int row = idx >> 5, ch = idx & 31;
            cp16(Vb + row * 136 + ch * 4, Vg + row * 128 + ch * 4);
        }
    };

    uint32_t qa[8][4];
    {
        const int qrow = qb * 64 + lw * 16 + r;
        #pragma unroll
        for (int kt = 0; kt < 8; kt++) {
            int d = kt * 8 + c;
            qa[kt][0] = f2tf(Q[base + qrow * HEAD + d] * QSCALE);
            qa[kt][1] = f2tf(Q[base + (qrow + 8) * HEAD + d] * QSCALE);
            qa[kt][2] = f2tf(Q[base + qrow * HEAD + d + 4] * QSCALE);
            qa[kt][3] = f2tf(Q[base + (qrow + 8) * HEAD + d + 4] * QSCALE);
        }
    }

    float oacc[8][4] = {};
    float mA = -1e30f, mB = -1e30f, lA = 0.0f, lB = 0.0f;

    if (g <= qb) {
        pfK(g); CP_COMMIT();
        pfV(g); CP_COMMIT();
    }

    for (int kb = g; kb <= qb; kb += 2) {
        CP_WAIT1();
        barg(g);

        float sacc[8][4] = {};
        #pragma unroll
        for (int dk = 0; dk < 8; dk++) {
            #pragma unroll
            for (int nt = 0; nt < 8; nt++) {
                float2 kk = *(const float2*)(Kb + (nt * 8 + r) * 72 + dk * 8 + 2 * c);
                uint32_t bfrag[2] = { __float_as_uint(kk.x), __float_as_uint(kk.y) };
                mma_tf32(sacc[nt], qa[dk], bfrag);
            }
        }

        barg(g);
        if (kb + 2 <= qb) pfK(kb + 2);
        CP_COMMIT();

        if (kb == qb) {
            int qA = lw * 16 + r;
            int qB = qA + 8;
            #pragma unroll
            for (int nt = 0; nt < 8; nt++) {
                int k0l = nt * 8 + 2 * c;
                if (k0l     > qA) sacc[nt][0] = -1e30f;
                if (k0l + 1 > qA) sacc[nt][1] = -1e30f;
                if (k0l     > qB) sacc[nt][2] = -1e30f;
                if (k0l + 1 > qB) sacc[nt][3] = -1e30f;
            }
        }

        {
            float mxA = -1e30f, mxB = -1e30f;
            #pragma unroll
            for (int nt = 0; nt < 8; nt++) {
                mxA = fmaxf(mxA, fmaxf(sacc[nt][0], sacc[nt][1]));
                mxB = fmaxf(mxB, fmaxf(sacc[nt][2], sacc[nt][3]));
            }
            mxA = fmaxf(mxA, __shfl_xor_sync(0xffffffffu, mxA, 1, 4));
            mxA = fmaxf(mxA, __shfl_xor_sync(0xffffffffu, mxA, 2, 4));
            mxB = fmaxf(mxB, __shfl_xor_sync(0xffffffffu, mxB, 1, 4));
            mxB = fmaxf(mxB, __shfl_xor_sync(0xffffffffu, mxB, 2, 4));
            float mnA = fmaxf(mA, mxA);
            float mnB = fmaxf(mB, mxB);
            float alA = ex2(mA - mnA);
            float alB = ex2(mB - mnB);
            mA = mnA; mB = mnB;
            float rsA = 0.0f, rsB = 0.0f;
            #pragma unroll
            for (int nt = 0; nt < 8; nt++) {
                sacc[nt][0] = ex2(sacc[nt][0] - mnA);
                sacc[nt][1] = ex2(sacc[nt][1] - mnA);
                sacc[nt][2] = ex2(sacc[nt][2] - mnB);
                sacc[nt][3] = ex2(sacc[nt][3] - mnB);
                rsA += sacc[nt][0] + sacc[nt][1];
                rsB += sacc[nt][2] + sacc[nt][3];
            }
            rsA += __shfl_xor_sync(0xffffffffu, rsA, 1, 4);
            rsA += __shfl_xor_sync(0xffffffffu, rsA, 2, 4);
            rsB += __shfl_xor_sync(0xffffffffu, rsB, 1, 4);
            rsB += __shfl_xor_sync(0xffffffffu, rsB, 2, 4);
            lA = lA * alA + rsA;
            lB = lB * alB + rsB;
            #pragma unroll
            for (int dt = 0; dt < 8; dt++) {
                oacc[dt][0] *= alA; oacc[dt][1] *= alA;
                oacc[dt][2] *= alB; oacc[dt][3] *= alB;
            }
        }

        #pragma unroll
        for (int nt = 0; nt < 8; nt++) {
            int col = nt * 8 + 2 * c;
            uint2 p0, p1;
            p0.x = f2tf(sacc[nt][0]); p0.y = f2tf(sacc[nt][1]);
            p1.x = f2tf(sacc[nt][2]); p1.y = f2tf(sacc[nt][3]);
            *(uint2*)&Psw[r * 68 + col]       = p0;
            *(uint2*)&Psw[(r + 8) * 68 + col] = p1;
        }
        __syncwarp();

        CP_WAIT1();
        barg(g);

        #pragma unroll
        for (int kt = 0; kt < 8; kt++) {
            uint32_t pa[4];
            pa[0] = __float_as_uint(Psw[r * 68 + kt * 8 + c]);
            pa[1] = __float_as_uint(Psw[(r + 8) * 68 + kt * 8 + c]);
            pa[2] = __float_as_uint(Psw[r * 68 + kt * 8 + c + 4]);
            pa[3] = __float_as_uint(Psw[(r + 8) * 68 + kt * 8 + c + 4]);
            #pragma unroll
            for (int dt = 0; dt < 8; dt++) {
                float2 vv = *(const float2*)(Vb + (kt * 4 + c) * 136 + (dt * 8 + r) * 2);
                uint32_t vbf[2] = { __float_as_uint(vv.x), __float_as_uint(vv.y) };
                mma_tf32(oacc[dt], pa, vbf);
            }
        }

        barg(g);
        if (kb + 2 <= qb) pfV(kb + 2);
        CP_COMMIT();
    }

    // ---- merge split-KV partials ----
    float* MS = sm;
    __syncthreads();
    if (g == 1) {
        float* p = MS + t128 * 37;
        #pragma unroll
        for (int dt = 0; dt < 8; dt++) {
            p[dt * 4 + 0] = oacc[dt][0]; p[dt * 4 + 1] = oacc[dt][1];
            p[dt * 4 + 2] = oacc[dt][2]; p[dt * 4 + 3] = oacc[dt][3];
        }
        p[32] = mA; p[33] = mB; p[34] = lA; p[35] = lB;
    }
    __syncthreads();
    if (g == 0) {
        const float* p = MS + t128 * 37;
        float m1A = p[32], m1B = p[33], l1A = p[34], l1B = p[35];
        float mnA = fmaxf(mA, m1A);
        float mnB = fmaxf(mB, m1B);
        float w0A = ex2(mA - mnA), w1A = ex2(m1A - mnA);
        float w0B = ex2(mB - mnB), w1B = ex2(m1B - mnB);
        float invA = 1.0f / (lA * w0A + l1A * w1A);
        float invB = 1.0f / (lB * w0B + l1B * w1B);
        int qrow = qb * 64 + lw * 16 + r;
        #pragma unroll
        for (int dt = 0; dt < 8; dt++) {
            float o0 = (oacc[dt][0] * w0A + p[dt * 4 + 0] * w1A) * invA;
            float o1 = (oacc[dt][1] * w0A + p[dt * 4 + 1] * w1A) * invA;
            float o2 = (oacc[dt][2] * w0B + p[dt * 4 + 2] * w1B) * invB;
            float o3 = (oacc[dt][3] * w0B + p[dt * 4 + 3] * w1B) * invB;
            int d = dt * 8 + 2 * c;
            *(float2*)&out[base + qrow * HEAD + d]       = make_float2(o0, o1);
            *(float2*)&out[base + (qrow + 8) * HEAD + d] = make_float2(o2, o3);
        }
    }
}

// ---------------------------------------------------------------------------
extern "C" void kernel_launch(void* const* d_in, const int* in_sizes, int n_in,
                              void* d_out, int out_size)
{
    const float* x  = (const float*)d_in[0];
    const float* Wq = (const float*)d_in[1];
    const float* bq = (const float*)d_in[2];
    const float* Wk = (const float*)d_in[3];
    const float* bk = (const float*)d_in[4];
    const float* Wv = (const float*)d_in[5];
    const float* bv = (const float*)d_in[6];
    float* out = (float*)d_out;

    cudaFuncSetAttribute(qkv_kernel,
        cudaFuncAttributeMaxDynamicSharedMemorySize, QKV_SMEM_BYTES);
    cudaFuncSetAttribute(attn_kernel,
        cudaFuncAttributeMaxDynamicSharedMemorySize, ATT_SMEM_BYTES);

    dim3 gw(EMB * HEAD / 256, 3);
    wprep_kernel<<<gw, 256>>>(Wq, Wk, Wv);

    qkv_kernel<<<M_TOTAL / 64, 256, QKV_SMEM_BYTES>>>(x, bq, bk, bv);

    dim3 g2(S_LEN / 64, BATCH);
    attn_kernel<<<g2, 256, ATT_SMEM_BYTES>>>(out);
}

// round 15
// speedup vs baseline: 1.1830x; 1.0149x over previous
#include <cuda_runtime.h>
#include <cstdint>

#define S_LEN 4096
#define EMB   1024
#define HEAD  64
#define BATCH 4
#define M_TOTAL (BATCH * S_LEN)   // 16384

__device__ float g_QKV[3][M_TOTAL * HEAD];
__device__ float g_W[3][EMB * HEAD];       // pre-rounded, b-frag-paired layout

// ---------------------------------------------------------------------------
// helpers
// ---------------------------------------------------------------------------
__device__ __forceinline__ uint32_t f2tf(float f) {
    uint32_t r;
    asm("cvt.rna.tf32.f32 %0, %1;" : "=r"(r) : "f"(f));
    return r;
}

__device__ __forceinline__ float ex2(float x) {
    float y;
    asm("ex2.approx.f32 %0, %1;" : "=f"(y) : "f"(x));
    return y;
}

__device__ __forceinline__ void mma_tf32(float c[4],
                                         const uint32_t a[4],
                                         const uint32_t b[2]) {
    asm volatile(
        "mma.sync.aligned.m16n8k8.row.col.f32.tf32.tf32.f32 "
        "{%0,%1,%2,%3}, {%4,%5,%6,%7}, {%8,%9}, {%0,%1,%2,%3};\n"
        : "+f"(c[0]), "+f"(c[1]), "+f"(c[2]), "+f"(c[3])
        : "r"(a[0]), "r"(a[1]), "r"(a[2]), "r"(a[3]),
          "r"(b[0]), "r"(b[1]));
}

__device__ __forceinline__ void cp16(float* s, const float* g) {
    uint32_t sa = (uint32_t)__cvta_generic_to_shared(s);
    asm volatile("cp.async.cg.shared.global [%0], [%1], 16;\n"
                 :: "r"(sa), "l"(g));
}
#define CP_COMMIT() asm volatile("cp.async.commit_group;\n")
#define CP_WAIT0()  asm volatile("cp.async.wait_group 0;\n")
#define CP_WAIT1()  asm volatile("cp.async.wait_group 1;\n")

__device__ __forceinline__ void barg(int g) {   // per-group named barrier
    asm volatile("bar.sync %0, 128;" :: "r"(g + 1) : "memory");
}

// ---------------------------------------------------------------------------
// Kernel 0: W prep. RNA-round W to tf32, paired layout:
//   (k, n) -> g_W[which][((k>>3)*64 + n)*8 + 2*(u&3) + (u>>2)], u = k&7
// Transposed mapping: each thread owns one (a, n) pair -> gathers 8 k-values
// (loads coalesced across lanes per u), writes the 8-word group as 2xSTG.128
// (lane stride 32B -> sectors fully written, no amplification).
// grid = (32, 3), 256 thr.
// ---------------------------------------------------------------------------
__global__ void wprep_kernel(const float* __restrict__ Wq,
                             const float* __restrict__ Wk,
                             const float* __restrict__ Wv)
{
    const float* src = (blockIdx.y == 0) ? Wq : (blockIdx.y == 1) ? Wk : Wv;
    float* dst = g_W[blockIdx.y];
    int tid = blockIdx.x * 256 + threadIdx.x;   // 0 .. 8191
    int a = tid >> 6;                            // k-group 0..127
    int n = tid & 63;
    float4 lo, hi;
    float* lop = (float*)&lo;
    float* hip = (float*)&hi;
    #pragma unroll
    for (int u = 0; u < 8; u++) {
        float v = src[(a * 8 + u) * HEAD + n];   // coalesced across lanes
        int p = 2 * (u & 3) + (u >> 2);          // paired position 0..7
        if (p < 4) lop[p] = __uint_as_float(f2tf(v));
        else       hip[p - 4] = __uint_as_float(f2tf(v));
    }
    *(float4*)&dst[(a * 64 + n) * 8]     = lo;
    *(float4*)&dst[(a * 64 + n) * 8 + 4] = hi;
}

// ---------------------------------------------------------------------------
// Kernel 1: FUSED QKV projection (BM=64, BK=32, 256 thr, 8 warps:
// 4 m-tiles x 2 n-halves; 256 blocks -> full chip). Unchanged from R14.
// ---------------------------------------------------------------------------
#define QKV_AS(buf)  (sm + (buf) * 2304)          // 64*36
#define QKV_BS(buf)  (sm + 4608 + (buf) * 6144)   // 12*512
#define QKV_SMEM_BYTES 67584

__global__ __launch_bounds__(256) void qkv_kernel(const float* __restrict__ x,
    const float* __restrict__ bq, const float* __restrict__ bk,
    const float* __restrict__ bv)
{
    extern __shared__ float sm[];

    const int t    = threadIdx.x;
    const int lane = t & 31;
    const int warp = t >> 5;
    const int m0   = (warp >> 1) * 16;
    const int n0   = (warp & 1) * 32;
    const int row0 = blockIdx.x * 64;

    const int r = lane >> 2;
    const int c = lane & 3;

    auto prefetch = [&](int k0, int buf) {
        float* Ab = QKV_AS(buf);
        float* Bb = QKV_BS(buf);
        #pragma unroll
        for (int i = 0; i < 2; i++) {              // 512 cp16: x tile 64x32
            int idx = t + 256 * i;
            int m = idx >> 3, ch = idx & 7;
            cp16(Ab + m * 36 + ch * 4, x + (row0 + m) * EMB + k0 + ch * 4);
        }
        const int s = k0 >> 5;
        #pragma unroll
        for (int i = 0; i < 6; i++) {              // 1536 cp16: 3 W tiles
            int idx = t + 256 * i;
            int blk = idx >> 7;                    // which*4 + a
            int off = (idx & 127) * 4;
            cp16(Bb + blk * 512 + off,
                 g_W[blk >> 2] + ((s * 4 + (blk & 3)) * 512 + off));
        }
    };

    float acc[3][4][4] = {};

    prefetch(0, 0);
    CP_COMMIT();

    for (int step = 0; step < 32; step++) {
        const int cur = step & 1;
        CP_WAIT0();
        __syncthreads();
        if (step < 31) { prefetch((step + 1) * 32, cur ^ 1); CP_COMMIT(); }

        const float* Ab = QKV_AS(cur);
        const float* Bb = QKV_BS(cur);

        #pragma unroll
        for (int ks = 0; ks < 4; ks++) {
            const float* ap = Ab + (m0 + r) * 36 + ks * 8 + c;
            uint32_t af[4];
            af[0] = f2tf(ap[0]);
            af[1] = f2tf(ap[8 * 36]);
            af[2] = f2tf(ap[4]);
            af[3] = f2tf(ap[8 * 36 + 4]);
            #pragma unroll
            for (int w = 0; w < 3; w++) {
                #pragma unroll
                for (int nt = 0; nt < 4; nt++) {
                    float2 bb = *(const float2*)(Bb + (w * 4 + ks) * 512 +
                                                 (n0 + nt * 8 + r) * 8 + 2 * c);
                    uint32_t bf[2] = { __float_as_uint(bb.x),
                                       __float_as_uint(bb.y) };
                    mma_tf32(acc[w][nt], af, bf);
                }
            }
        }
        __syncthreads();
    }

    // ---- epilogue: +bias, per-which output layouts ----
    const int j  = 2 * c;
    const int p0 = 2 * (j & 3) + (j >> 2);
    const int p1 = 2 * ((j + 1) & 3) + ((j + 1) >> 2);
    const int mA = row0 + m0 + r;
    const int mB = mA + 8;

    #pragma unroll
    for (int w = 0; w < 3; w++) {
        const float* bias = (w == 0) ? bq : (w == 1) ? bk : bv;
        float* out = g_QKV[w];
        #pragma unroll
        for (int nt = 0; nt < 4; nt++) {
            int n = n0 + nt * 8 + 2 * c;
            float b0 = bias[n], b1 = bias[n + 1];
            float v00 = acc[w][nt][0] + b0, v01 = acc[w][nt][1] + b1;
            float v10 = acc[w][nt][2] + b0, v11 = acc[w][nt][3] + b1;

            if (w == 0) {
                *(float2*)&out[mA * HEAD + n] = make_float2(v00, v01);
                *(float2*)&out[mB * HEAD + n] = make_float2(v10, v11);
            } else if (w == 1) {
                int base8 = n0 + nt * 8;
                out[mA * HEAD + base8 + p0] = __uint_as_float(f2tf(v00));
                out[mA * HEAD + base8 + p1] = __uint_as_float(f2tf(v01));
                out[mB * HEAD + base8 + p0] = __uint_as_float(f2tf(v10));
                out[mB * HEAD + base8 + p1] = __uint_as_float(f2tf(v11));
            } else {
                int baseA = (mA >> 3) * 512 + (mA & 3) * 128 + ((mA >> 2) & 1);
                int baseB = (mB >> 3) * 512 + (mB & 3) * 128 + ((mB >> 2) & 1);
                out[baseA + 2 * n]       = __uint_as_float(f2tf(v00));
                out[baseA + 2 * (n + 1)] = __uint_as_float(f2tf(v01));
                out[baseB + 2 * n]       = __uint_as_float(f2tf(v10));
                out[baseB + 2 * (n + 1)] = __uint_as_float(f2tf(v11));
            }
        }
    }
}

// ---------------------------------------------------------------------------
// Kernel 2: causal flash attention (R11 body). Remap v2:
//   singles (lids 108..147, 8-warp SMs): qb 38..47  (was 34..43)
//   heavy pairs: qb 48..63 + qb 0..15   (sum 63)
//   mid pairs:   qb 27..37 + qb 16..26  (sum 53)
// ---------------------------------------------------------------------------
#define ATT_KG(g)   (sm + (g) * 8960)
#define ATT_VG(g)   (sm + (g) * 8960 + 4608)
#define ATT_PS      (sm + 17920)
#define ATT_SMEM_BYTES 106496

#define QSCALE 0.1803368801111354f    // (1/8) * log2(e)

__global__ __launch_bounds__(256, 2) void attn_kernel(float* __restrict__ out)
{
    extern __shared__ float sm[];

    const float* Q = g_QKV[0];
    const float* K = g_QKV[1];
    const float* V = g_QKV[2];

    // ---- rebalanced work remap v2 (classic placement: SM = lid % 148) ----
    const int lid = blockIdx.x + 64 * blockIdx.y;   // 0..255
    int qb, b;
    if (lid < 64)        { qb = 63 - (lid >> 2);              b = lid & 3; }
    else if (lid < 108)  { int k = lid - 64;  qb = 37 - (k >> 2); b = k & 3; }
    else if (lid < 148)  { int k = lid - 108; qb = 38 + (k >> 2); b = k & 3; }
    else if (lid < 212)  { int k = lid - 148; qb = k >> 2;        b = k & 3; }
    else                 { int k = lid - 212; qb = 16 + (k >> 2); b = k & 3; }

    const int t    = threadIdx.x;
    const int lane = t & 31;
    const int warp = t >> 5;
    const int g    = warp >> 2;
    const int lw   = warp & 3;
    const int t128 = t & 127;
    const int base = b * S_LEN * HEAD;

    const int r = lane >> 2;
    const int c = lane & 3;

    float* Kb  = ATT_KG(g);
    float* Vb  = ATT_VG(g);
    float* Psw = ATT_PS + warp * 1088;

    auto pfK = [&](int kb) {
        const float* Kg = K + base + kb * 64 * HEAD;
        #pragma unroll
        for (int i = 0; i < 8; i++) {
            int idx = t128 + 128 * i;
            int row = idx >> 4, ch = idx & 15;
            cp16(Kb + row * 72 + ch * 4, Kg + row * 64 + ch * 4);
        }
    };
    auto pfV = [&](int kb) {
        const float* Vg = V + base + kb * 64 * HEAD;
        #pragma unroll
        for (int i = 0; i < 8; i++) {
            int idx = t128 + 128 * i;
            int row = idx >> 5, ch = idx & 31;
            cp16(Vb + row * 136 + ch * 4, Vg + row * 128 + ch * 4);
        }
    };

    uint32_t qa[8][4];
    {
        const int qrow = qb * 64 + lw * 16 + r;
        #pragma unroll
        for (int kt = 0; kt < 8; kt++) {
            int d = kt * 8 + c;
            qa[kt][0] = f2tf(Q[base + qrow * HEAD + d] * QSCALE);
            qa[kt][1] = f2tf(Q[base + (qrow + 8) * HEAD + d] * QSCALE);
            qa[kt][2] = f2tf(Q[base + qrow * HEAD + d + 4] * QSCALE);
            qa[kt][3] = f2tf(Q[base + (qrow + 8) * HEAD + d + 4] * QSCALE);
        }
    }

    float oacc[8][4] = {};
    float mA = -1e30f, mB = -1e30f, lA = 0.0f, lB = 0.0f;

    if (g <= qb) {
        pfK(g); CP_COMMIT();
        pfV(g); CP_COMMIT();
    }

    for (int kb = g; kb <= qb; kb += 2) {
        CP_WAIT1();
        barg(g);

        float sacc[8][4] = {};
        #pragma unroll
        for (int dk = 0; dk < 8; dk++) {
            #pragma unroll
            for (int nt = 0; nt < 8; nt++) {
                float2 kk = *(const float2*)(Kb + (nt * 8 + r) * 72 + dk * 8 + 2 * c);
                uint32_t bfrag[2] = { __float_as_uint(kk.x), __float_as_uint(kk.y) };
                mma_tf32(sacc[nt], qa[dk], bfrag);
            }
        }

        barg(g);
        if (kb + 2 <= qb) pfK(kb + 2);
        CP_COMMIT();

        if (kb == qb) {
            int qA = lw * 16 + r;
            int qB = qA + 8;
            #pragma unroll
            for (int nt = 0; nt < 8; nt++) {
                int k0l = nt * 8 + 2 * c;
                if (k0l     > qA) sacc[nt][0] = -1e30f;
                if (k0l + 1 > qA) sacc[nt][1] = -1e30f;
                if (k0l     > qB) sacc[nt][2] = -1e30f;
                if (k0l + 1 > qB) sacc[nt][3] = -1e30f;
            }
        }

        {
            float mxA = -1e30f, mxB = -1e30f;
            #pragma unroll
            for (int nt = 0; nt < 8; nt++) {
                mxA = fmaxf(mxA, fmaxf(sacc[nt][0], sacc[nt][1]));
                mxB = fmaxf(mxB, fmaxf(sacc[nt][2], sacc[nt][3]));
            }
            mxA = fmaxf(mxA, __shfl_xor_sync(0xffffffffu, mxA, 1, 4));
            mxA = fmaxf(mxA, __shfl_xor_sync(0xffffffffu, mxA, 2, 4));
            mxB = fmaxf(mxB, __shfl_xor_sync(0xffffffffu, mxB, 1, 4));
            mxB = fmaxf(mxB, __shfl_xor_sync(0xffffffffu, mxB, 2, 4));
            float mnA = fmaxf(mA, mxA);
            float mnB = fmaxf(mB, mxB);
            float alA = ex2(mA - mnA);
            float alB = ex2(mB - mnB);
            mA = mnA; mB = mnB;
            float rsA = 0.0f, rsB = 0.0f;
            #pragma unroll
            for (int nt = 0; nt < 8; nt++) {
                sacc[nt][0] = ex2(sacc[nt][0] - mnA);
                sacc[nt][1] = ex2(sacc[nt][1] - mnA);
                sacc[nt][2] = ex2(sacc[nt][2] - mnB);
                sacc[nt][3] = ex2(sacc[nt][3] - mnB);
                rsA += sacc[nt][0] + sacc[nt][1];
                rsB += sacc[nt][2] + sacc[nt][3];
            }
            rsA += __shfl_xor_sync(0xffffffffu, rsA, 1, 4);
            rsA += __shfl_xor_sync(0xffffffffu, rsA, 2, 4);
            rsB += __shfl_xor_sync(0xffffffffu, rsB, 1, 4);
            rsB += __shfl_xor_sync(0xffffffffu, rsB, 2, 4);
            lA = lA * alA + rsA;
            lB = lB * alB + rsB;
            #pragma unroll
            for (int dt = 0; dt < 8; dt++) {
                oacc[dt][0] *= alA; oacc[dt][1] *= alA;
                oacc[dt][2] *= alB; oacc[dt][3] *= alB;
            }
        }

        #pragma unroll
        for (int nt = 0; nt < 8; nt++) {
            int col = nt * 8 + 2 * c;
            uint2 p0, p1;
            p0.x = f2tf(sacc[nt][0]); p0.y = f2tf(sacc[nt][1]);
            p1.x = f2tf(sacc[nt][2]); p1.y = f2tf(sacc[nt][3]);
            *(uint2*)&Psw[r * 68 + col]       = p0;
            *(uint2*)&Psw[(r + 8) * 68 + col] = p1;
        }
        __syncwarp();

        CP_WAIT1();
        barg(g);

        #pragma unroll
        for (int kt = 0; kt < 8; kt++) {
            uint32_t pa[4];
            pa[0] = __float_as_uint(Psw[r * 68 + kt * 8 + c]);
            pa[1] = __float_as_uint(Psw[(r + 8) * 68 + kt * 8 + c]);
            pa[2] = __float_as_uint(Psw[r * 68 + kt * 8 + c + 4]);
            pa[3] = __float_as_uint(Psw[(r + 8) * 68 + kt * 8 + c + 4]);
            #pragma unroll
            for (int dt = 0; dt < 8; dt++) {
                float2 vv = *(const float2*)(Vb + (kt * 4 + c) * 136 + (dt * 8 + r) * 2);
                uint32_t vbf[2] = { __float_as_uint(vv.x), __float_as_uint(vv.y) };
                mma_tf32(oacc[dt], pa, vbf);
            }
        }

        barg(g);
        if (kb + 2 <= qb) pfV(kb + 2);
        CP_COMMIT();
    }

    // ---- merge split-KV partials ----
    float* MS = sm;
    __syncthreads();
    if (g == 1) {
        float* p = MS + t128 * 37;
        #pragma unroll
        for (int dt = 0; dt < 8; dt++) {
            p[dt * 4 + 0] = oacc[dt][0]; p[dt * 4 + 1] = oacc[dt][1];
            p[dt * 4 + 2] = oacc[dt][2]; p[dt * 4 + 3] = oacc[dt][3];
        }
        p[32] = mA; p[33] = mB; p[34] = lA; p[35] = lB;
    }
    __syncthreads();
    if (g == 0) {
        const float* p = MS + t128 * 37;
        float m1A = p[32], m1B = p[33], l1A = p[34], l1B = p[35];
        float mnA = fmaxf(mA, m1A);
        float mnB = fmaxf(mB, m1B);
        float w0A = ex2(mA - mnA), w1A = ex2(m1A - mnA);
        float w0B = ex2(mB - mnB), w1B = ex2(m1B - mnB);
        float invA = 1.0f / (lA * w0A + l1A * w1A);
        float invB = 1.0f / (lB * w0B + l1B * w1B);
        int qrow = qb * 64 + lw * 16 + r;
        #pragma unroll
        for (int dt = 0; dt < 8; dt++) {
            float o0 = (oacc[dt][0] * w0A + p[dt * 4 + 0] * w1A) * invA;
            float o1 = (oacc[dt][1] * w0A + p[dt * 4 + 1] * w1A) * invA;
            float o2 = (oacc[dt][2] * w0B + p[dt * 4 + 2] * w1B) * invB;
            float o3 = (oacc[dt][3] * w0B + p[dt * 4 + 3] * w1B) * invB;
            int d = dt * 8 + 2 * c;
            *(float2*)&out[base + qrow * HEAD + d]       = make_float2(o0, o1);
            *(float2*)&out[base + (qrow + 8) * HEAD + d] = make_float2(o2, o3);
        }
    }
}

// ---------------------------------------------------------------------------
extern "C" void kernel_launch(void* const* d_in, const int* in_sizes, int n_in,
                              void* d_out, int out_size)
{
    const float* x  = (const float*)d_in[0];
    const float* Wq = (const float*)d_in[1];
    const float* bq = (const float*)d_in[2];
    const float* Wk = (const float*)d_in[3];
    const float* bk = (const float*)d_in[4];
    const float* Wv = (const float*)d_in[5];
    const float* bv = (const float*)d_in[6];
    float* out = (float*)d_out;

    cudaFuncSetAttribute(qkv_kernel,
        cudaFuncAttributeMaxDynamicSharedMemorySize, QKV_SMEM_BYTES);
    cudaFuncSetAttribute(attn_kernel,
        cudaFuncAttributeMaxDynamicSharedMemorySize, ATT_SMEM_BYTES);

    dim3 gw(32, 3);
    wprep_kernel<<<gw, 256>>>(Wq, Wk, Wv);

    qkv_kernel<<<M_TOTAL / 64, 256, QKV_SMEM_BYTES>>>(x, bq, bk, bv);

    dim3 g2(S_LEN / 64, BATCH);
    attn_kernel<<<g2, 256, ATT_SMEM_BYTES>>>(out);
}